// round 16
// baseline (speedup 1.0000x reference)
#include <cuda_runtime.h>
#include <cuda_bf16.h>
#include <math.h>
#include <stdint.h>

#define T_LEN 1024
#define K_LEN 1024
#define H_DIM 256
#define E_DIM 64
#define TOPIC 100
#define EXLEN 768
#define GRU_IN 201   // 2*TOPIC + 1
#define TOPK 64

// ---------------- device scratch ----------------
__device__ float g_v[TOPIC];
__device__ float g_kn[E_DIM];
__device__ float g_betaall[T_LEN];
__device__ float g_adot[K_LEN];
__device__ float g_beta[TOPK];
__device__ int   g_topidx[TOPK];
__device__ float g_alpha[K_LEN];
__device__ float g_u[3 * H_DIM];
__device__ float g_score;
__device__ unsigned g_f1;       // k1-done counter (target 21)
__device__ unsigned g_f2;       // dots-done counter (target 352)
__device__ float g_gh[K_LEN * 3 * H_DIM];

__device__ __forceinline__ unsigned f2tf32(float f) {
    unsigned r;
    asm("cvt.rna.tf32.f32 %0, %1;" : "=r"(r) : "f"(f));
    return r;
}

__device__ __forceinline__ uint32_t smem_u32(const void* p) {
    uint32_t a;
    asm("{ .reg .u64 t; cvta.to.shared.u64 t, %1; cvt.u32.u64 %0, t; }"
        : "=r"(a) : "l"(p));
    return a;
}

__device__ __forceinline__ void mma_tf32(float* c, const unsigned* a, const unsigned* b) {
    asm volatile(
        "mma.sync.aligned.m16n8k8.row.col.f32.tf32.tf32.f32 "
        "{%0,%1,%2,%3}, {%4,%5,%6,%7}, {%8,%9}, {%0,%1,%2,%3};\n"
        : "+f"(c[0]), "+f"(c[1]), "+f"(c[2]), "+f"(c[3])
        : "r"(a[0]), "r"(a[1]), "r"(a[2]), "r"(a[3]), "r"(b[0]), "r"(b[1]));
}

// ======================= kA: k1 + GEMM + dots + select ====================
// bids 0..20   : k1 embed (v, kn), then bump g_f1
// bids 21..116 : tf32 GEMM (no deps, starts immediately)
// bids 117..468: dots (spin g_f1==21), then bump g_f2
// bid 469      : top-k + softmaxes (spin g_f2==352), then reset flags
#define KA_K1   21
#define KA_GEMM 96
#define KA_DOT  352
#define KA_TOTAL (KA_K1 + KA_GEMM + KA_DOT + 1)   // 470
#define GBM 128
#define GBN 64

__global__ void kA_front(const float* __restrict__ W_resize,
                         const float* __restrict__ b_resize,
                         const float* __restrict__ ex_e,
                         const float* __restrict__ Wk,
                         const float* __restrict__ bk,
                         const float* __restrict__ co_e,
                         const float* __restrict__ vs,
                         const float* __restrict__ km,
                         const float* __restrict__ W_ih,
                         const float* __restrict__ s_ptr,
                         const float* __restrict__ A,   // h0 [1024,256]
                         const float* __restrict__ B) { // W_hh [768,256]
    __shared__ union {
        struct { unsigned As[GBM][36]; unsigned Bs[GBN][36]; } g;
        struct {
            unsigned long long skey[T_LEN];
            float sv2[TOPK];
            int   si2[TOPK];
            float sred[8];
        } s;
    } sm;
    int tid = threadIdx.x;
    int bid = blockIdx.x;
    int lane = tid & 31;

    if (bid < KA_K1) {
        // ---------------- k1: v, kn ----------------
        int gw = bid * 8 + (tid >> 5);
        if (bid == 0 && tid == 0) g_score = 0.f;
        if (gw < TOPIC) {
            const float* wr = W_resize + gw * EXLEN;
            float p = 0.f;
            for (int i = lane; i < EXLEN; i += 32) p += wr[i] * ex_e[i];
            #pragma unroll
            for (int o = 16; o; o >>= 1) p += __shfl_xor_sync(0xffffffffu, p, o);
            if (lane == 0) g_v[gw] = p + b_resize[gw];
        } else if (gw < TOPIC + E_DIM) {
            int row = gw - TOPIC;
            const float* wr = Wk + row * K_LEN;
            float p = 0.f;
            for (int i = lane; i < K_LEN; i += 32) p += wr[i] * co_e[i];
            #pragma unroll
            for (int o = 16; o; o >>= 1) p += __shfl_xor_sync(0xffffffffu, p, o);
            if (lane == 0) g_kn[row] = p + bk[row];
        }
        __syncthreads();
        if (tid == 0) { __threadfence(); atomicAdd(&g_f1, 1u); }
    } else if (bid < KA_K1 + KA_GEMM) {
        // ---------------- tf32 MMA GEMM: g_gh = h0 @ W_hh^T ----------------
        int bi = bid - KA_K1;          // 0..95
        int nblk = bi % 12;
        int mblk = bi / 12;
        int m0 = mblk * GBM, n0 = nblk * GBN;
        int wid = tid >> 5;
        int wm = (wid & 3) * 32, wn = (wid >> 2) * 32;
        int g = lane >> 2, tg = lane & 3;
        int lr = tid >> 3;
        int lc4 = (tid & 7) * 4;

        float c[2][4][4];
        #pragma unroll
        for (int mt = 0; mt < 2; mt++)
            #pragma unroll
            for (int nt = 0; nt < 4; nt++)
                #pragma unroll
                for (int i = 0; i < 4; i++) c[mt][nt][i] = 0.f;

        for (int kt = 0; kt < H_DIM; kt += 32) {
            float4 a4[4], b4[2];
            #pragma unroll
            for (int i = 0; i < 4; i++)
                a4[i] = *(const float4*)(A + (size_t)(m0 + lr + 32 * i) * H_DIM + kt + lc4);
            #pragma unroll
            for (int i = 0; i < 2; i++)
                b4[i] = *(const float4*)(B + (size_t)(n0 + lr + 32 * i) * H_DIM + kt + lc4);
            __syncthreads();
            #pragma unroll
            for (int i = 0; i < 4; i++) {
                sm.g.As[lr + 32 * i][lc4 + 0] = f2tf32(a4[i].x);
                sm.g.As[lr + 32 * i][lc4 + 1] = f2tf32(a4[i].y);
                sm.g.As[lr + 32 * i][lc4 + 2] = f2tf32(a4[i].z);
                sm.g.As[lr + 32 * i][lc4 + 3] = f2tf32(a4[i].w);
            }
            #pragma unroll
            for (int i = 0; i < 2; i++) {
                sm.g.Bs[lr + 32 * i][lc4 + 0] = f2tf32(b4[i].x);
                sm.g.Bs[lr + 32 * i][lc4 + 1] = f2tf32(b4[i].y);
                sm.g.Bs[lr + 32 * i][lc4 + 2] = f2tf32(b4[i].z);
                sm.g.Bs[lr + 32 * i][lc4 + 3] = f2tf32(b4[i].w);
            }
            __syncthreads();
            #pragma unroll
            for (int ks = 0; ks < 32; ks += 8) {
                unsigned afr[2][4], bfr[4][2];
                #pragma unroll
                for (int mt = 0; mt < 2; mt++) {
                    int r0 = wm + mt * 16 + g;
                    afr[mt][0] = sm.g.As[r0][ks + tg];
                    afr[mt][1] = sm.g.As[r0 + 8][ks + tg];
                    afr[mt][2] = sm.g.As[r0][ks + tg + 4];
                    afr[mt][3] = sm.g.As[r0 + 8][ks + tg + 4];
                }
                #pragma unroll
                for (int nt = 0; nt < 4; nt++) {
                    int r0 = wn + nt * 8 + g;
                    bfr[nt][0] = sm.g.Bs[r0][ks + tg];
                    bfr[nt][1] = sm.g.Bs[r0][ks + tg + 4];
                }
                #pragma unroll
                for (int mt = 0; mt < 2; mt++)
                    #pragma unroll
                    for (int nt = 0; nt < 4; nt++)
                        mma_tf32(c[mt][nt], afr[mt], bfr[nt]);
            }
        }
        #pragma unroll
        for (int mt = 0; mt < 2; mt++) {
            int row = m0 + wm + mt * 16 + g;
            #pragma unroll
            for (int nt = 0; nt < 4; nt++) {
                int col = n0 + wn + nt * 8 + 2 * tg;
                *(float2*)(g_gh + (size_t)row * (3 * H_DIM) + col)
                    = make_float2(c[mt][nt][0], c[mt][nt][1]);
                *(float2*)(g_gh + (size_t)(row + 8) * (3 * H_DIM) + col)
                    = make_float2(c[mt][nt][2], c[mt][nt][3]);
            }
        }
    } else if (bid < KA_K1 + KA_GEMM + KA_DOT) {
        // ---------------- dots: beta_all, adot, u (after k1) ----------------
        if (tid == 0) {
            volatile unsigned* f = &g_f1;
            while (*f < (unsigned)KA_K1) { }
        }
        __syncthreads();

        int gw = (bid - KA_K1 - KA_GEMM) * 8 + (tid >> 5);
        if (gw < T_LEN) {
            const float* vr = vs + gw * TOPIC;
            float p = 0.f;
            for (int i = lane; i < TOPIC; i += 32) p += vr[i] * g_v[i];
            #pragma unroll
            for (int o = 16; o; o >>= 1) p += __shfl_xor_sync(0xffffffffu, p, o);
            if (lane == 0) g_betaall[gw] = p;
        } else if (gw < 2 * T_LEN) {
            int row = gw - T_LEN;
            const float* kr = km + row * E_DIM;
            float p = 0.f;
            for (int i = lane; i < E_DIM; i += 32) p += kr[i] * g_kn[i];
            #pragma unroll
            for (int o = 16; o; o >>= 1) p += __shfl_xor_sync(0xffffffffu, p, o);
            if (lane == 0) g_adot[row] = p;
        } else if (gw < 2 * T_LEN + 3 * H_DIM) {
            int row = gw - 2 * T_LEN;
            float s = s_ptr[0];
            float mask = (s >= 0.5f) ? 1.f : 0.f;
            const float* wr = W_ih + row * GRU_IN;
            float p = 0.f;
            for (int i = lane; i < GRU_IN; i += 32) {
                float xv = (i < TOPIC) ? g_v[i] * mask
                         : (i < 2 * TOPIC) ? g_v[i - TOPIC] * (1.f - mask) : s;
                p += wr[i] * xv;
            }
            #pragma unroll
            for (int o = 16; o; o >>= 1) p += __shfl_xor_sync(0xffffffffu, p, o);
            if (lane == 0) g_u[row] = p;
        }
        __syncthreads();
        if (tid == 0) { __threadfence(); atomicAdd(&g_f2, 1u); }
    } else {
        // ---------------- select: top-k + softmaxes (after dots) ----------
        if (tid == 0) {
            volatile unsigned* f = &g_f2;
            while (*f < (unsigned)KA_DOT) { }
        }
        __syncthreads();

        // load keys (4 per thread)
        for (int i = tid; i < T_LEN; i += 256) {
            float bv = g_betaall[i];
            unsigned u = __float_as_uint(bv);
            u = (u & 0x80000000u) ? ~u : (u | 0x80000000u);
            sm.s.skey[i] = ((unsigned long long)u << 32) | (unsigned)i;
        }
        __syncthreads();

        // bitonic sort descending (smem compare-exchange, 4 pairs/thread)
        for (int k = 2; k <= T_LEN; k <<= 1) {
            for (int j = k >> 1; j > 0; j >>= 1) {
                #pragma unroll
                for (int base = 0; base < T_LEN; base += 256) {
                    int idx = base + tid;
                    int ixj = idx ^ j;
                    if (ixj > idx) {
                        unsigned long long a = sm.s.skey[idx];
                        unsigned long long b = sm.s.skey[ixj];
                        bool up = (idx & k) == 0;
                        bool sw = up ? (a < b) : (a > b);
                        if (sw) { sm.s.skey[idx] = b; sm.s.skey[ixj] = a; }
                    }
                }
                __syncthreads();
            }
        }

        if (tid < TOPK) {
            unsigned long long key = sm.s.skey[tid];
            unsigned su = (unsigned)(key >> 32);
            float val = __uint_as_float((su & 0x80000000u) ? (su ^ 0x80000000u) : ~su);
            sm.s.sv2[tid] = val;
            sm.s.si2[tid] = (int)(key & 0xffffffffu);
        }
        __syncthreads();

        if (tid < 32) {   // softmax over top-64
            float m  = sm.s.sv2[0];
            float e0 = __expf(sm.s.sv2[lane] - m);
            float e1 = __expf(sm.s.sv2[lane + 32] - m);
            float smv = e0 + e1;
            #pragma unroll
            for (int o = 16; o; o >>= 1) smv += __shfl_xor_sync(0xffffffffu, smv, o);
            g_beta[lane]        = e0 / smv;
            g_beta[lane + 32]   = e1 / smv;
            g_topidx[lane]      = sm.s.si2[lane];
            g_topidx[lane + 32] = sm.s.si2[lane + 32];
        }

        // alpha = softmax(g_adot), 4 values/thread, two-level reduce
        float dv[4];
        float lmax = -1e30f;
        #pragma unroll
        for (int q = 0; q < 4; q++) {
            dv[q] = g_adot[tid + 256 * q];
            lmax = fmaxf(lmax, dv[q]);
        }
        #pragma unroll
        for (int o = 16; o; o >>= 1) lmax = fmaxf(lmax, __shfl_xor_sync(0xffffffffu, lmax, o));
        if (lane == 0) sm.s.sred[tid >> 5] = lmax;
        __syncthreads();
        if (tid < 8) {
            float x = sm.s.sred[tid];
            #pragma unroll
            for (int o = 4; o; o >>= 1) x = fmaxf(x, __shfl_xor_sync(0xffu, x, o));
            if (tid == 0) sm.s.sred[0] = x;
        }
        __syncthreads();
        float mx = sm.s.sred[0];
        __syncthreads();
        float lsum = 0.f;
        float ev[4];
        #pragma unroll
        for (int q = 0; q < 4; q++) { ev[q] = __expf(dv[q] - mx); lsum += ev[q]; }
        #pragma unroll
        for (int o = 16; o; o >>= 1) lsum += __shfl_xor_sync(0xffffffffu, lsum, o);
        if (lane == 0) sm.s.sred[tid >> 5] = lsum;
        __syncthreads();
        if (tid < 8) {
            float x = sm.s.sred[tid];
            #pragma unroll
            for (int o = 4; o; o >>= 1) x += __shfl_xor_sync(0xffu, x, o);
            if (tid == 0) sm.s.sred[0] = x;
        }
        __syncthreads();
        float tot = sm.s.sred[0];
        #pragma unroll
        for (int q = 0; q < 4; q++) g_alpha[tid + 256 * q] = ev[q] / tot;

        // reset flags for next replay (sole consumer; all producers done)
        __syncthreads();
        if (tid == 0) { g_f1 = 0u; g_f2 = 0u; }
    }
}

// ---------------- K4: TMA-pipelined gather + scalar-score epilogue -------
#define STAGE_BYTES 16384
#define STAGE_ROWS  16
#define CHUNK_ROWS  128
#define NITER       (CHUNK_ROWS / STAGE_ROWS)   // 8

__global__ void k4_gather(const float* __restrict__ hs,
                          const float* __restrict__ W_score) {
    extern __shared__ __align__(16) char dynsm[];      // 2 x STAGE_BYTES
    __shared__ float sal[CHUNK_ROWS];
    __shared__ float4 sacc[256];
    __shared__ float swsum[2];
    __shared__ unsigned long long mbar[2];

    int tid = threadIdx.x;
    int bid = blockIdx.x;
    int j = bid & 63;
    int chunk = bid >> 6;
    int kk0 = chunk * CHUNK_ROWS;

    if (tid < CHUNK_ROWS) sal[tid] = g_alpha[kk0 + tid];

    uint32_t mb0 = smem_u32(&mbar[0]);
    uint32_t mb1 = smem_u32(&mbar[1]);
    uint32_t stg_base = smem_u32(dynsm);

    int slice = g_topidx[j];
    const char* src = (const char*)hs
                    + (size_t)slice * (K_LEN * H_DIM * 4)
                    + (size_t)kk0 * (H_DIM * 4);

    if (tid == 0) {
        asm volatile("mbarrier.init.shared.b64 [%0], 1;" :: "r"(mb0) : "memory");
        asm volatile("mbarrier.init.shared.b64 [%0], 1;" :: "r"(mb1) : "memory");
        asm volatile("fence.proxy.async.shared::cta;" ::: "memory");
    }
    __syncthreads();

    if (tid == 0) {
        asm volatile("mbarrier.arrive.expect_tx.shared.b64 _, [%0], %1;"
                     :: "r"(mb0), "r"((unsigned)STAGE_BYTES) : "memory");
        asm volatile("cp.async.bulk.shared::cluster.global.mbarrier::complete_tx::bytes "
                     "[%0], [%1], %2, [%3];"
                     :: "r"(stg_base), "l"(src), "r"((unsigned)STAGE_BYTES), "r"(mb0)
                     : "memory");
        asm volatile("mbarrier.arrive.expect_tx.shared.b64 _, [%0], %1;"
                     :: "r"(mb1), "r"((unsigned)STAGE_BYTES) : "memory");
        asm volatile("cp.async.bulk.shared::cluster.global.mbarrier::complete_tx::bytes "
                     "[%0], [%1], %2, [%3];"
                     :: "r"(stg_base + STAGE_BYTES), "l"(src + STAGE_BYTES),
                        "r"((unsigned)STAGE_BYTES), "r"(mb1)
                     : "memory");
    }

    int t4 = tid & 63;
    int rg = tid >> 6;
    float4 acc = make_float4(0.f, 0.f, 0.f, 0.f);

    for (int it = 0; it < NITER; it++) {
        int st = it & 1;
        unsigned par = (unsigned)((it >> 1) & 1);
        uint32_t mb = st ? mb1 : mb0;
        asm volatile(
            "{\n\t.reg .pred P;\n"
            "WL_%=:\n\t"
            "mbarrier.try_wait.parity.shared::cta.b64 P, [%0], %1;\n\t"
            "@!P bra WL_%=;\n\t}"
            :: "r"(mb), "r"(par) : "memory");

        const float4* stg = (const float4*)(dynsm + st * STAGE_BYTES);
        int rbase = it * STAGE_ROWS;
        #pragma unroll
        for (int m = 0; m < 4; m++) {
            int r = rg + 4 * m;
            float a = sal[rbase + r];
            float4 vv = stg[r * (H_DIM / 4) + t4];
            acc.x = fmaf(a, vv.x, acc.x); acc.y = fmaf(a, vv.y, acc.y);
            acc.z = fmaf(a, vv.z, acc.z); acc.w = fmaf(a, vv.w, acc.w);
        }
        __syncthreads();
        if (tid == 0 && it + 2 < NITER) {
            const char* nsrc = src + (size_t)(it + 2) * STAGE_BYTES;
            asm volatile("mbarrier.arrive.expect_tx.shared.b64 _, [%0], %1;"
                         :: "r"(mb), "r"((unsigned)STAGE_BYTES) : "memory");
            asm volatile("cp.async.bulk.shared::cluster.global.mbarrier::complete_tx::bytes "
                         "[%0], [%1], %2, [%3];"
                         :: "r"(stg_base + st * STAGE_BYTES), "l"(nsrc),
                            "r"((unsigned)STAGE_BYTES), "r"(mb)
                         : "memory");
        }
    }

    sacc[tid] = acc;
    __syncthreads();
    if (tid < 64) {
        float4 a0 = sacc[tid], a1 = sacc[64 + tid];
        float4 a2 = sacc[128 + tid], a3 = sacc[192 + tid];
        float px = a0.x + a1.x + a2.x + a3.x;
        float py = a0.y + a1.y + a2.y + a3.y;
        float pz = a0.z + a1.z + a2.z + a3.z;
        float pw = a0.w + a1.w + a2.w + a3.w;
        const float4 ws = *(const float4*)(W_score + TOPIC + tid * 4);
        float d = px * ws.x + py * ws.y + pz * ws.z + pw * ws.w;
        #pragma unroll
        for (int o = 16; o; o >>= 1) d += __shfl_xor_sync(0xffffffffu, d, o);
        if ((tid & 31) == 0) swsum[tid >> 5] = d;
    }
    __syncthreads();
    if (tid == 0) {
        atomicAdd(&g_score, g_beta[j] * (swsum[0] + swsum[1]));
    }
}

// ---------------- K5: GRU gates + h_new + predict_score ------------------
__global__ void k5_gru(const float* __restrict__ h0,
                       const float* __restrict__ b_ih,
                       const float* __restrict__ b_hh,
                       const float* __restrict__ W_score,
                       const float* __restrict__ b_score,
                       float* __restrict__ out) {
    int kk = blockIdx.x;
    int hh = threadIdx.x;
    float a = g_alpha[kk];
    const float* gh = g_gh + (size_t)kk * (3 * H_DIM);

    float gir = fmaf(a, g_u[hh],             b_ih[hh]);
    float giz = fmaf(a, g_u[H_DIM + hh],     b_ih[H_DIM + hh]);
    float gin = fmaf(a, g_u[2 * H_DIM + hh], b_ih[2 * H_DIM + hh]);
    float ghr = gh[hh]             + b_hh[hh];
    float ghz = gh[H_DIM + hh]     + b_hh[H_DIM + hh];
    float ghn = gh[2 * H_DIM + hh] + b_hh[2 * H_DIM + hh];

    float r = 1.f / (1.f + __expf(-(gir + ghr)));
    float z = 1.f / (1.f + __expf(-(giz + ghz)));
    float n = tanhf(gin + r * ghn);
    float h0v = h0[(size_t)kk * H_DIM + hh];
    out[1 + (size_t)kk * H_DIM + hh] = (1.f - z) * n + z * h0v;

    if (kk == 0 && hh < 32) {
        float p = 0.f;
        for (int i = hh; i < TOPIC; i += 32) p += W_score[i] * g_v[i];
        #pragma unroll
        for (int o = 16; o; o >>= 1) p += __shfl_xor_sync(0xffffffffu, p, o);
        if (hh == 0) out[0] = p + g_score + b_score[0];
    }
}

// ---------------------------------------------------------------------------
extern "C" void kernel_launch(void* const* d_in, const int* in_sizes, int n_in,
                              void* d_out, int out_size) {
    const float* co_e     = (const float*)d_in[0];
    const float* ex_e     = (const float*)d_in[1];
    const float* s        = (const float*)d_in[2];
    const float* h        = (const float*)d_in[3];
    const float* vs       = (const float*)d_in[4];
    const float* hs       = (const float*)d_in[5];
    const float* W_resize = (const float*)d_in[6];
    const float* b_resize = (const float*)d_in[7];
    const float* Wk       = (const float*)d_in[8];
    const float* bk       = (const float*)d_in[9];
    const float* km       = (const float*)d_in[10];
    const float* W_score  = (const float*)d_in[11];
    const float* b_score  = (const float*)d_in[12];
    const float* W_ih     = (const float*)d_in[13];
    const float* W_hh     = (const float*)d_in[14];
    const float* b_ih     = (const float*)d_in[15];
    const float* b_hh     = (const float*)d_in[16];
    float* out = (float*)d_out;

    kA_front <<<KA_TOTAL, 256>>>(W_resize, b_resize, ex_e, Wk, bk, co_e,
                                 vs, km, W_ih, s, h, W_hh);
    k4_gather<<<512, 256, 2 * STAGE_BYTES>>>(hs, W_score);
    k5_gru   <<<K_LEN, 256>>>(h, b_ih, b_hh, W_score, b_score, out);
}

// round 17
// speedup vs baseline: 1.2128x; 1.2128x over previous
#include <cuda_runtime.h>
#include <cuda_bf16.h>
#include <math.h>
#include <stdint.h>

#define T_LEN 1024
#define K_LEN 1024
#define H_DIM 256
#define E_DIM 64
#define TOPIC 100
#define EXLEN 768
#define GRU_IN 201   // 2*TOPIC + 1
#define TOPK 64

// ---------------- device scratch ----------------
__device__ float g_v[TOPIC];
__device__ float g_kn[E_DIM];
__device__ float g_betaall[T_LEN];
__device__ float g_adot[K_LEN];
__device__ float g_beta[TOPK];
__device__ int   g_topidx[TOPK];
__device__ float g_alpha[K_LEN];
__device__ float g_u[3 * H_DIM];
__device__ float g_score;
__device__ unsigned g_cnt;
__device__ float g_gh[K_LEN * 3 * H_DIM];

__device__ __forceinline__ unsigned f2tf32(float f) {
    unsigned r;
    asm("cvt.rna.tf32.f32 %0, %1;" : "=r"(r) : "f"(f));
    return r;
}

__device__ __forceinline__ uint32_t smem_u32(const void* p) {
    uint32_t a;
    asm("{ .reg .u64 t; cvta.to.shared.u64 t, %1; cvt.u32.u64 %0, t; }"
        : "=r"(a) : "l"(p));
    return a;
}

// ---------------- K1: v = W_resize@ex_e + b ; kn = Wk@co_e + bk ----------
__global__ void k1_embed(const float* __restrict__ W_resize,
                         const float* __restrict__ b_resize,
                         const float* __restrict__ ex_e,
                         const float* __restrict__ Wk,
                         const float* __restrict__ bk,
                         const float* __restrict__ co_e) {
    int lane = threadIdx.x & 31;
    int gw = blockIdx.x * 8 + (threadIdx.x >> 5);
    if (blockIdx.x == 0 && threadIdx.x == 0) { g_score = 0.f; g_cnt = 0u; }
    if (gw < TOPIC) {
        const float* wr = W_resize + gw * EXLEN;
        float p = 0.f;
        for (int i = lane; i < EXLEN; i += 32) p += wr[i] * ex_e[i];
        #pragma unroll
        for (int o = 16; o; o >>= 1) p += __shfl_xor_sync(0xffffffffu, p, o);
        if (lane == 0) g_v[gw] = p + b_resize[gw];
    } else if (gw < TOPIC + E_DIM) {
        int row = gw - TOPIC;
        const float* wr = Wk + row * K_LEN;
        float p = 0.f;
        for (int i = lane; i < K_LEN; i += 32) p += wr[i] * co_e[i];
        #pragma unroll
        for (int o = 16; o; o >>= 1) p += __shfl_xor_sync(0xffffffffu, p, o);
        if (lane == 0) g_kn[row] = p + bk[row];
    }
}

// ---- K2: dots (352 blocks) + independent tf32 GEMM (96 blocks) ----------
#define DOT_BLOCKS 352
#define GBM 128
#define GBN 64

__device__ __forceinline__ void mma_tf32(float* c, const unsigned* a, const unsigned* b) {
    asm volatile(
        "mma.sync.aligned.m16n8k8.row.col.f32.tf32.tf32.f32 "
        "{%0,%1,%2,%3}, {%4,%5,%6,%7}, {%8,%9}, {%0,%1,%2,%3};\n"
        : "+f"(c[0]), "+f"(c[1]), "+f"(c[2]), "+f"(c[3])
        : "r"(a[0]), "r"(a[1]), "r"(a[2]), "r"(a[3]), "r"(b[0]), "r"(b[1]));
}

__global__ void k2_dots_gemm(const float* __restrict__ vs,
                             const float* __restrict__ km,
                             const float* __restrict__ W_ih,
                             const float* __restrict__ s_ptr,
                             const float* __restrict__ A,   // h0 [1024,256]
                             const float* __restrict__ B) { // W_hh [768,256]
    __shared__ struct { unsigned As[GBM][36]; unsigned Bs[GBN][36]; } smg;
    int tid = threadIdx.x;

    if (blockIdx.x < DOT_BLOCKS) {
        int lane = tid & 31;
        int gw = blockIdx.x * 8 + (tid >> 5);
        if (gw < T_LEN) {
            const float* vr = vs + gw * TOPIC;
            float p = 0.f;
            for (int i = lane; i < TOPIC; i += 32) p += vr[i] * g_v[i];
            #pragma unroll
            for (int o = 16; o; o >>= 1) p += __shfl_xor_sync(0xffffffffu, p, o);
            if (lane == 0) g_betaall[gw] = p;
        } else if (gw < 2 * T_LEN) {
            int row = gw - T_LEN;
            const float* kr = km + row * E_DIM;
            float p = 0.f;
            for (int i = lane; i < E_DIM; i += 32) p += kr[i] * g_kn[i];
            #pragma unroll
            for (int o = 16; o; o >>= 1) p += __shfl_xor_sync(0xffffffffu, p, o);
            if (lane == 0) g_adot[row] = p;
        } else if (gw < 2 * T_LEN + 3 * H_DIM) {
            int row = gw - 2 * T_LEN;
            float s = s_ptr[0];
            float mask = (s >= 0.5f) ? 1.f : 0.f;
            const float* wr = W_ih + row * GRU_IN;
            float p = 0.f;
            for (int i = lane; i < GRU_IN; i += 32) {
                float xv = (i < TOPIC) ? g_v[i] * mask
                         : (i < 2 * TOPIC) ? g_v[i - TOPIC] * (1.f - mask) : s;
                p += wr[i] * xv;
            }
            #pragma unroll
            for (int o = 16; o; o >>= 1) p += __shfl_xor_sync(0xffffffffu, p, o);
            if (lane == 0) g_u[row] = p;
        }
    } else {
        // ---- tf32 MMA GEMM ----
        int bi = blockIdx.x - DOT_BLOCKS;     // 0..95
        int nblk = bi % 12;
        int mblk = bi / 12;
        int m0 = mblk * GBM, n0 = nblk * GBN;
        int lane = tid & 31, wid = tid >> 5;
        int wm = (wid & 3) * 32, wn = (wid >> 2) * 32;
        int g = lane >> 2, tg = lane & 3;
        int lr = tid >> 3;
        int lc4 = (tid & 7) * 4;

        float c[2][4][4];
        #pragma unroll
        for (int mt = 0; mt < 2; mt++)
            #pragma unroll
            for (int nt = 0; nt < 4; nt++)
                #pragma unroll
                for (int i = 0; i < 4; i++) c[mt][nt][i] = 0.f;

        for (int kt = 0; kt < H_DIM; kt += 32) {
            float4 a4[4], b4[2];
            #pragma unroll
            for (int i = 0; i < 4; i++)
                a4[i] = *(const float4*)(A + (size_t)(m0 + lr + 32 * i) * H_DIM + kt + lc4);
            #pragma unroll
            for (int i = 0; i < 2; i++)
                b4[i] = *(const float4*)(B + (size_t)(n0 + lr + 32 * i) * H_DIM + kt + lc4);
            __syncthreads();
            #pragma unroll
            for (int i = 0; i < 4; i++) {
                smg.As[lr + 32 * i][lc4 + 0] = f2tf32(a4[i].x);
                smg.As[lr + 32 * i][lc4 + 1] = f2tf32(a4[i].y);
                smg.As[lr + 32 * i][lc4 + 2] = f2tf32(a4[i].z);
                smg.As[lr + 32 * i][lc4 + 3] = f2tf32(a4[i].w);
            }
            #pragma unroll
            for (int i = 0; i < 2; i++) {
                smg.Bs[lr + 32 * i][lc4 + 0] = f2tf32(b4[i].x);
                smg.Bs[lr + 32 * i][lc4 + 1] = f2tf32(b4[i].y);
                smg.Bs[lr + 32 * i][lc4 + 2] = f2tf32(b4[i].z);
                smg.Bs[lr + 32 * i][lc4 + 3] = f2tf32(b4[i].w);
            }
            __syncthreads();
            #pragma unroll
            for (int ks = 0; ks < 32; ks += 8) {
                unsigned afr[2][4], bfr[4][2];
                #pragma unroll
                for (int mt = 0; mt < 2; mt++) {
                    int r0 = wm + mt * 16 + g;
                    afr[mt][0] = smg.As[r0][ks + tg];
                    afr[mt][1] = smg.As[r0 + 8][ks + tg];
                    afr[mt][2] = smg.As[r0][ks + tg + 4];
                    afr[mt][3] = smg.As[r0 + 8][ks + tg + 4];
                }
                #pragma unroll
                for (int nt = 0; nt < 4; nt++) {
                    int r0 = wn + nt * 8 + g;
                    bfr[nt][0] = smg.Bs[r0][ks + tg];
                    bfr[nt][1] = smg.Bs[r0][ks + tg + 4];
                }
                #pragma unroll
                for (int mt = 0; mt < 2; mt++)
                    #pragma unroll
                    for (int nt = 0; nt < 4; nt++)
                        mma_tf32(c[mt][nt], afr[mt], bfr[nt]);
            }
        }
        #pragma unroll
        for (int mt = 0; mt < 2; mt++) {
            int row = m0 + wm + mt * 16 + g;
            #pragma unroll
            for (int nt = 0; nt < 4; nt++) {
                int col = n0 + wn + nt * 8 + 2 * tg;
                *(float2*)(g_gh + (size_t)row * (3 * H_DIM) + col)
                    = make_float2(c[mt][nt][0], c[mt][nt][1]);
                *(float2*)(g_gh + (size_t)(row + 8) * (3 * H_DIM) + col)
                    = make_float2(c[mt][nt][2], c[mt][nt][3]);
            }
        }
    }
}

// ---------------- K3: hybrid bitonic top-k + softmaxes -------------------
__global__ void k3_select() {
    __shared__ unsigned long long skey[T_LEN];
    __shared__ float sv2[TOPK];
    __shared__ int   si2[TOPK];
    __shared__ float sred[32];
    int tid = threadIdx.x, lane = tid & 31, wid = tid >> 5;

    float bv = g_betaall[tid];
    unsigned u = __float_as_uint(bv);
    u = (u & 0x80000000u) ? ~u : (u | 0x80000000u);
    unsigned long long key = ((unsigned long long)u << 32) | (unsigned)tid;

    for (int k = 2; k <= T_LEN; k <<= 1) {
        for (int j = k >> 1; j > 0; j >>= 1) {
            bool keepmax = (((tid & k) == 0) == ((tid & j) == 0));
            unsigned long long p;
            if (j >= 32) {
                skey[tid] = key;
                __syncthreads();
                p = skey[tid ^ j];
                __syncthreads();
            } else {
                p = __shfl_xor_sync(0xffffffffu, key, j);
            }
            unsigned long long hi = (key > p) ? key : p;
            unsigned long long lo = (key > p) ? p : key;
            key = keepmax ? hi : lo;
        }
    }

    if (tid < TOPK) {
        unsigned su = (unsigned)(key >> 32);
        float val = __uint_as_float((su & 0x80000000u) ? (su ^ 0x80000000u) : ~su);
        sv2[tid] = val;
        si2[tid] = (int)(key & 0xffffffffu);
    }
    __syncthreads();

    if (tid < 32) {
        float m  = sv2[0];
        float e0 = __expf(sv2[lane] - m);
        float e1 = __expf(sv2[lane + 32] - m);
        float sm = e0 + e1;
        #pragma unroll
        for (int o = 16; o; o >>= 1) sm += __shfl_xor_sync(0xffffffffu, sm, o);
        g_beta[lane]        = e0 / sm;
        g_beta[lane + 32]   = e1 / sm;
        g_topidx[lane]      = si2[lane];
        g_topidx[lane + 32] = si2[lane + 32];
    }

    float dv = g_adot[tid];
    float wmax = dv;
    #pragma unroll
    for (int o = 16; o; o >>= 1) wmax = fmaxf(wmax, __shfl_xor_sync(0xffffffffu, wmax, o));
    if (lane == 0) sred[wid] = wmax;
    __syncthreads();
    if (tid < 32) {
        float x = sred[lane];
        #pragma unroll
        for (int o = 16; o; o >>= 1) x = fmaxf(x, __shfl_xor_sync(0xffffffffu, x, o));
        if (lane == 0) sred[0] = x;
    }
    __syncthreads();
    float mx = sred[0];
    __syncthreads();
    float ev = __expf(dv - mx);
    float ws = ev;
    #pragma unroll
    for (int o = 16; o; o >>= 1) ws += __shfl_xor_sync(0xffffffffu, ws, o);
    if (lane == 0) sred[wid] = ws;
    __syncthreads();
    if (tid < 32) {
        float x = sred[lane];
        #pragma unroll
        for (int o = 16; o; o >>= 1) x += __shfl_xor_sync(0xffffffffu, x, o);
        if (lane == 0) sred[0] = x;
    }
    __syncthreads();
    g_alpha[tid] = ev / sred[0];
}

// ---- K4: fused [TMA gather + score, 512 blocks] + [GRU, 1024 blocks] ----
#define STAGE_BYTES 16384
#define STAGE_ROWS  16
#define CHUNK_ROWS  128
#define NITER       (CHUNK_ROWS / STAGE_ROWS)   // 8
#define GATHER_BLOCKS 512

__global__ void k4_fused(const float* __restrict__ hs,
                         const float* __restrict__ W_score,
                         const float* __restrict__ b_score,
                         const float* __restrict__ h0,
                         const float* __restrict__ b_ih,
                         const float* __restrict__ b_hh,
                         float* __restrict__ out) {
    extern __shared__ __align__(16) char dynsm[];      // 2 x STAGE_BYTES
    __shared__ float sal[CHUNK_ROWS];
    __shared__ float4 sacc[256];
    __shared__ float swsum[2];
    __shared__ unsigned long long mbar[2];
    __shared__ int sdone;

    int tid = threadIdx.x;
    int bid = blockIdx.x;

    if (bid < GATHER_BLOCKS) {
        // ================= TMA-pipelined gather + scalar score ============
        int j = bid & 63;
        int chunk = bid >> 6;
        int kk0 = chunk * CHUNK_ROWS;

        if (tid < CHUNK_ROWS) sal[tid] = g_alpha[kk0 + tid];

        uint32_t mb0 = smem_u32(&mbar[0]);
        uint32_t mb1 = smem_u32(&mbar[1]);
        uint32_t stg_base = smem_u32(dynsm);

        int slice = g_topidx[j];
        const char* src = (const char*)hs
                        + (size_t)slice * (K_LEN * H_DIM * 4)
                        + (size_t)kk0 * (H_DIM * 4);

        if (tid == 0) {
            asm volatile("mbarrier.init.shared.b64 [%0], 1;" :: "r"(mb0) : "memory");
            asm volatile("mbarrier.init.shared.b64 [%0], 1;" :: "r"(mb1) : "memory");
            asm volatile("fence.proxy.async.shared::cta;" ::: "memory");
        }
        __syncthreads();

        if (tid == 0) {
            asm volatile("mbarrier.arrive.expect_tx.shared.b64 _, [%0], %1;"
                         :: "r"(mb0), "r"((unsigned)STAGE_BYTES) : "memory");
            asm volatile("cp.async.bulk.shared::cluster.global.mbarrier::complete_tx::bytes "
                         "[%0], [%1], %2, [%3];"
                         :: "r"(stg_base), "l"(src), "r"((unsigned)STAGE_BYTES), "r"(mb0)
                         : "memory");
            asm volatile("mbarrier.arrive.expect_tx.shared.b64 _, [%0], %1;"
                         :: "r"(mb1), "r"((unsigned)STAGE_BYTES) : "memory");
            asm volatile("cp.async.bulk.shared::cluster.global.mbarrier::complete_tx::bytes "
                         "[%0], [%1], %2, [%3];"
                         :: "r"(stg_base + STAGE_BYTES), "l"(src + STAGE_BYTES),
                            "r"((unsigned)STAGE_BYTES), "r"(mb1)
                         : "memory");
        }

        int t4 = tid & 63;
        int rg = tid >> 6;
        float4 acc = make_float4(0.f, 0.f, 0.f, 0.f);

        for (int it = 0; it < NITER; it++) {
            int st = it & 1;
            unsigned par = (unsigned)((it >> 1) & 1);
            uint32_t mb = st ? mb1 : mb0;
            asm volatile(
                "{\n\t.reg .pred P;\n"
                "WL_%=:\n\t"
                "mbarrier.try_wait.parity.shared::cta.b64 P, [%0], %1;\n\t"
                "@!P bra WL_%=;\n\t}"
                :: "r"(mb), "r"(par) : "memory");

            const float4* stg = (const float4*)(dynsm + st * STAGE_BYTES);
            int rbase = it * STAGE_ROWS;
            #pragma unroll
            for (int m = 0; m < 4; m++) {
                int r = rg + 4 * m;
                float a = sal[rbase + r];
                float4 vv = stg[r * (H_DIM / 4) + t4];
                acc.x = fmaf(a, vv.x, acc.x); acc.y = fmaf(a, vv.y, acc.y);
                acc.z = fmaf(a, vv.z, acc.z); acc.w = fmaf(a, vv.w, acc.w);
            }
            __syncthreads();
            if (tid == 0 && it + 2 < NITER) {
                const char* nsrc = src + (size_t)(it + 2) * STAGE_BYTES;
                asm volatile("mbarrier.arrive.expect_tx.shared.b64 _, [%0], %1;"
                             :: "r"(mb), "r"((unsigned)STAGE_BYTES) : "memory");
                asm volatile("cp.async.bulk.shared::cluster.global.mbarrier::complete_tx::bytes "
                             "[%0], [%1], %2, [%3];"
                             :: "r"(stg_base + st * STAGE_BYTES), "l"(nsrc),
                                "r"((unsigned)STAGE_BYTES), "r"(mb)
                             : "memory");
            }
        }

        sacc[tid] = acc;
        __syncthreads();
        if (tid < 64) {
            float4 a0 = sacc[tid], a1 = sacc[64 + tid];
            float4 a2 = sacc[128 + tid], a3 = sacc[192 + tid];
            float px = a0.x + a1.x + a2.x + a3.x;
            float py = a0.y + a1.y + a2.y + a3.y;
            float pz = a0.z + a1.z + a2.z + a3.z;
            float pw = a0.w + a1.w + a2.w + a3.w;
            const float4 ws = *(const float4*)(W_score + TOPIC + tid * 4);
            float d = px * ws.x + py * ws.y + pz * ws.z + pw * ws.w;
            #pragma unroll
            for (int o = 16; o; o >>= 1) d += __shfl_xor_sync(0xffffffffu, d, o);
            if ((tid & 31) == 0) swsum[tid >> 5] = d;
        }
        __syncthreads();
        if (tid == 0) {
            atomicAdd(&g_score, g_beta[j] * (swsum[0] + swsum[1]));
            __threadfence();
            unsigned old = atomicAdd(&g_cnt, 1u);
            sdone = (old == GATHER_BLOCKS - 1) ? 1 : 0;
        }
        __syncthreads();
        if (sdone && tid < 32) {
            // last gather block finalizes predict_score
            float p = 0.f;
            for (int i = tid; i < TOPIC; i += 32) p += W_score[i] * g_v[i];
            #pragma unroll
            for (int o = 16; o; o >>= 1) p += __shfl_xor_sync(0xffffffffu, p, o);
            if (tid == 0) out[0] = p + __ldcg(&g_score) + b_score[0];
        }
    } else {
        // ================= GRU path: one block per kk row ==================
        int kk = bid - GATHER_BLOCKS;
        int hh = tid;
        float a = g_alpha[kk];
        const float* gh = g_gh + (size_t)kk * (3 * H_DIM);

        float gir = fmaf(a, g_u[hh],             b_ih[hh]);
        float giz = fmaf(a, g_u[H_DIM + hh],     b_ih[H_DIM + hh]);
        float gin = fmaf(a, g_u[2 * H_DIM + hh], b_ih[2 * H_DIM + hh]);
        float ghr = gh[hh]             + b_hh[hh];
        float ghz = gh[H_DIM + hh]     + b_hh[H_DIM + hh];
        float ghn = gh[2 * H_DIM + hh] + b_hh[2 * H_DIM + hh];

        float r = 1.f / (1.f + __expf(-(gir + ghr)));
        float z = 1.f / (1.f + __expf(-(giz + ghz)));
        float n = tanhf(gin + r * ghn);
        float h0v = h0[(size_t)kk * H_DIM + hh];
        out[1 + (size_t)kk * H_DIM + hh] = (1.f - z) * n + z * h0v;
    }
}

// ---------------------------------------------------------------------------
extern "C" void kernel_launch(void* const* d_in, const int* in_sizes, int n_in,
                              void* d_out, int out_size) {
    const float* co_e     = (const float*)d_in[0];
    const float* ex_e     = (const float*)d_in[1];
    const float* s        = (const float*)d_in[2];
    const float* h        = (const float*)d_in[3];
    const float* vs       = (const float*)d_in[4];
    const float* hs       = (const float*)d_in[5];
    const float* W_resize = (const float*)d_in[6];
    const float* b_resize = (const float*)d_in[7];
    const float* Wk       = (const float*)d_in[8];
    const float* bk       = (const float*)d_in[9];
    const float* km       = (const float*)d_in[10];
    const float* W_score  = (const float*)d_in[11];
    const float* b_score  = (const float*)d_in[12];
    const float* W_ih     = (const float*)d_in[13];
    const float* W_hh     = (const float*)d_in[14];
    const float* b_ih     = (const float*)d_in[15];
    const float* b_hh     = (const float*)d_in[16];
    float* out = (float*)d_out;

    k1_embed    <<<21, 256>>>(W_resize, b_resize, ex_e, Wk, bk, co_e);
    k2_dots_gemm<<<DOT_BLOCKS + 96, 256>>>(vs, km, W_ih, s, h, W_hh);
    k3_select   <<<1, 1024>>>();
    k4_fused    <<<GATHER_BLOCKS + K_LEN, 256, 2 * STAGE_BYTES>>>(
                    hs, W_score, b_score, h, b_ih, b_hh, out);
}